// round 5
// baseline (speedup 1.0000x reference)
#include <cuda_runtime.h>
#include <stdint.h>

#define BDIM    256      // batch rows
#define SDIM    2048     // sequence positions
#define VDIM    128000   // vocab
#define THREADS 512
#define PER     (SDIM / THREADS)   // 4 positions per thread
#define HSIZE   4096               // smem hash slots (load factor 0.5)
#define NWARPS  (THREADS / 32)

__device__ __forceinline__ float block_reduce_max(float v, float* red) {
    __syncthreads();
    #pragma unroll
    for (int o = 16; o; o >>= 1)
        v = fmaxf(v, __shfl_xor_sync(0xffffffffu, v, o));
    int w = threadIdx.x >> 5, l = threadIdx.x & 31;
    if (l == 0) red[w] = v;
    __syncthreads();
    if (w == 0) {
        v = (l < NWARPS) ? red[l] : -1e30f;
        #pragma unroll
        for (int o = 16; o; o >>= 1)
            v = fmaxf(v, __shfl_xor_sync(0xffffffffu, v, o));
        if (l == 0) red[0] = v;
    }
    __syncthreads();
    return red[0];
}

__device__ __forceinline__ float block_reduce_sum(float v, float* red) {
    __syncthreads();
    #pragma unroll
    for (int o = 16; o; o >>= 1)
        v += __shfl_xor_sync(0xffffffffu, v, o);
    int w = threadIdx.x >> 5, l = threadIdx.x & 31;
    if (l == 0) red[w] = v;
    __syncthreads();
    if (w == 0) {
        v = (l < NWARPS) ? red[l] : 0.0f;
        #pragma unroll
        for (int o = 16; o; o >>= 1)
            v += __shfl_xor_sync(0xffffffffu, v, o);
        if (l == 0) red[0] = v;
    }
    __syncthreads();
    return red[0];
}

// Softmax + dedup + scatter only. Zero-fill of w_a is done by cudaMemsetAsync
// before this kernel (same stream), which balances the 131 MB fill across the
// whole chip instead of tying it to 256 CTAs.
__global__ __launch_bounds__(THREADS, 2)
void ohwa_scatter_kernel(const float* __restrict__ w_es,
                         const int* __restrict__ x32,   // raw int32 view of x
                         float* __restrict__ out,
                         long long out_elems) {
    const int b = blockIdx.x;
    const int t = threadIdx.x;

    // dtype sniff: int64 little-endian high words are 0 for v < 2^31
    const bool is64 = (x32[1] | x32[3] | x32[5] | x32[7]) == 0;
    const int stride = is64 ? 2 : 1;
    const int* __restrict__ xrow = x32 + (size_t)b * SDIM * stride;

    float* __restrict__ w_a  = out + (size_t)b * VDIM;
    const float* __restrict__ wrow = w_es + (size_t)b * SDIM;

    __shared__ int   h_key[HSIZE];
    __shared__ int   h_pos[HSIZE];
    __shared__ float red[NWARPS];

    for (int i = t; i < HSIZE; i += THREADS) {
        h_key[i] = -1;
        h_pos[i] = -1;
    }
    // (first block_reduce begins with __syncthreads(), covering init)

    float e[PER];
    int   vv[PER];
    float m = -1e30f;
    #pragma unroll
    for (int j = 0; j < PER; j++) {
        int i = t + j * THREADS;
        e[j]  = wrow[i];
        vv[j] = xrow[i * stride];          // low word either way
        m = fmaxf(m, e[j]);
    }

    m = block_reduce_max(m, red);
    float s = 0.0f;
    #pragma unroll
    for (int j = 0; j < PER; j++) {
        e[j] = __expf(e[j] - m);
        s += e[j];
    }
    s = block_reduce_sum(s, red);
    float inv = __frcp_rn(s);

    long long wbase = (long long)BDIM * VDIM + (long long)b * SDIM;
    #pragma unroll
    for (int j = 0; j < PER; j++) {
        e[j] *= inv;
        long long o = wbase + t + j * THREADS;
        if (o < out_elems) out[o] = e[j];
    }

    // duplicate resolution: last position wins
    int slot[PER];
    #pragma unroll
    for (int j = 0; j < PER; j++) {
        int v = vv[j];
        int i = t + j * THREADS;
        if ((unsigned)v >= VDIM) { slot[j] = -1; continue; }
        unsigned sl = ((unsigned)v * 2654435761u) & (HSIZE - 1);
        while (true) {
            int k = h_key[sl];
            if (k == v) break;
            if (k == -1) {
                int old = atomicCAS(&h_key[sl], -1, v);
                if (old == -1 || old == v) break;
            }
            sl = (sl + 1) & (HSIZE - 1);
        }
        slot[j] = (int)sl;
        atomicMax(&h_pos[sl], i);
    }
    __syncthreads();

    #pragma unroll
    for (int j = 0; j < PER; j++) {
        int i = t + j * THREADS;
        if (slot[j] >= 0 && h_pos[slot[j]] == i)
            w_a[vv[j]] = e[j];
    }
}

extern "C" void kernel_launch(void* const* d_in, const int* in_sizes, int n_in,
                              void* d_out, int out_size) {
    const float* w_es = (const float*)d_in[0];
    const int*   x32  = (const int*)d_in[1];
    float*       out  = (float*)d_out;
    (void)in_sizes; (void)n_in;

    // Zero the w_a region [BDIM * VDIM floats] with the driver's tuned fill.
    size_t wa_bytes = (size_t)BDIM * VDIM * sizeof(float);
    cudaMemsetAsync(d_out, 0, wa_bytes);

    ohwa_scatter_kernel<<<BDIM, THREADS>>>(w_es, x32, out, (long long)out_size);
}

// round 6
// speedup vs baseline: 1.0885x; 1.0885x over previous
#include <cuda_runtime.h>
#include <stdint.h>

#define BDIM    256                 // batch rows
#define SDIM    2048                // sequence positions
#define VDIM    128000              // vocab
#define SEGS    16                  // segments per row
#define SEGF    (VDIM / SEGS)       // 8000 floats per segment
#define THREADS 256
#define PER     (SDIM / THREADS)    // 8 positions per thread
#define NWARPS  (THREADS / 32)      // 8

__device__ __forceinline__ float block_reduce_max(float v, float* red) {
    __syncthreads();
    #pragma unroll
    for (int o = 16; o; o >>= 1)
        v = fmaxf(v, __shfl_xor_sync(0xffffffffu, v, o));
    int w = threadIdx.x >> 5, l = threadIdx.x & 31;
    if (l == 0) red[w] = v;
    __syncthreads();
    if (w == 0) {
        v = (l < NWARPS) ? red[l] : -1e30f;
        #pragma unroll
        for (int o = 4; o; o >>= 1)
            v = fmaxf(v, __shfl_xor_sync(0xffffffffu, v, o));
        if (l == 0) red[0] = v;
    }
    __syncthreads();
    return red[0];
}

__device__ __forceinline__ float block_reduce_sum(float v, float* red) {
    __syncthreads();
    #pragma unroll
    for (int o = 16; o; o >>= 1)
        v += __shfl_xor_sync(0xffffffffu, v, o);
    int w = threadIdx.x >> 5, l = threadIdx.x & 31;
    if (l == 0) red[w] = v;
    __syncthreads();
    if (w == 0) {
        v = (l < NWARPS) ? red[l] : 0.0f;
        #pragma unroll
        for (int o = 4; o; o >>= 1)
            v += __shfl_xor_sync(0xffffffffu, v, o);
        if (l == 0) red[0] = v;
    }
    __syncthreads();
    return red[0];
}

// One CTA = one 8000-float segment of one row's w_a. Zero-fill + weight
// injection in a single streaming write pass: every output byte touched once.
__global__ __launch_bounds__(THREADS)
void ohwa_fused_kernel(const float* __restrict__ w_es,
                       const int* __restrict__ x32,   // raw int32 view of x
                       float* __restrict__ out,
                       long long out_elems) {
    const int s = blockIdx.x;          // segment
    const int b = blockIdx.y;          // row
    const int t = threadIdx.x;

    // dtype sniff: int64 little-endian high words are 0 for v < 2^31
    const bool is64 = (x32[1] | x32[3] | x32[5] | x32[7]) == 0;
    const int stride = is64 ? 2 : 1;
    const int* __restrict__ xrow = x32 + (size_t)b * SDIM * stride;
    const float* __restrict__ wrow = w_es + (size_t)b * SDIM;

    __shared__ int   pos[SEGF];        // winning position per vocab offset
    __shared__ float wsm[SDIM];        // this row's softmax weights
    __shared__ float red[NWARPS];

    // --- init pos to -1 (vectorized) ---
    int4* pos4 = reinterpret_cast<int4*>(pos);
    #pragma unroll 4
    for (int i = t; i < SEGF / 4; i += THREADS)
        pos4[i] = make_int4(-1, -1, -1, -1);

    // --- softmax over the row (redundant per segment; 8KB L2-shared) ---
    float e[PER];
    float m = -1e30f;
    #pragma unroll
    for (int j = 0; j < PER; j++) {
        e[j] = wrow[t + j * THREADS];
        m = fmaxf(m, e[j]);
    }
    m = block_reduce_max(m, red);      // leading syncthreads also covers pos init
    float sum = 0.0f;
    #pragma unroll
    for (int j = 0; j < PER; j++) {
        e[j] = __expf(e[j] - m);
        sum += e[j];
    }
    sum = block_reduce_sum(sum, red);
    float inv = __frcp_rn(sum);
    #pragma unroll
    for (int j = 0; j < PER; j++) {
        e[j] *= inv;
        wsm[t + j * THREADS] = e[j];
    }

    // --- scatter positions of tokens in my segment (last-wins via atomicMax) ---
    const int segbase = s * SEGF;
    #pragma unroll
    for (int j = 0; j < PER; j++) {
        int i = t + j * THREADS;
        int v = xrow[i * stride];      // low word either way (LE)
        unsigned off = (unsigned)(v - segbase);
        if (off < (unsigned)SEGF)
            atomicMax(&pos[off], i);
    }
    __syncthreads();                   // pos + wsm complete

    // --- streaming fill with injection: one float4 store per 4 outputs ---
    float4* __restrict__ dst =
        reinterpret_cast<float4*>(out + (size_t)b * VDIM + segbase);
    const int4* __restrict__ p4 = reinterpret_cast<const int4*>(pos);
    #pragma unroll 4
    for (int i = t; i < SEGF / 4; i += THREADS) {
        int4 p = p4[i];
        float4 v = make_float4(0.f, 0.f, 0.f, 0.f);
        if (p.x >= 0) v.x = wsm[p.x];
        if (p.y >= 0) v.y = wsm[p.y];
        if (p.z >= 0) v.z = wsm[p.z];
        if (p.w >= 0) v.w = wsm[p.w];
        dst[i] = v;
    }

    // --- weights output (segment 0 only) ---
    if (s == 0) {
        long long wbase = (long long)BDIM * VDIM + (long long)b * SDIM;
        #pragma unroll
        for (int j = 0; j < PER; j++) {
            long long o = wbase + t + j * THREADS;
            if (o < out_elems) out[o] = e[j];
        }
    }
}

extern "C" void kernel_launch(void* const* d_in, const int* in_sizes, int n_in,
                              void* d_out, int out_size) {
    const float* w_es = (const float*)d_in[0];
    const int*   x32  = (const int*)d_in[1];
    float*       out  = (float*)d_out;
    (void)in_sizes; (void)n_in;
    dim3 grid(SEGS, BDIM);
    ohwa_fused_kernel<<<grid, THREADS>>>(w_es, x32, out, (long long)out_size);
}